// round 13
// baseline (speedup 1.0000x reference)
#include <cuda_runtime.h>
#include <math.h>

#define En 2
#define NN 512
#define Bn 64
#define Tt 12
#define Kk 64
#define RN 4     // rows per block tile in main kernel
#define BG 4     // batches per block in main kernel
#define ESTR (Bn * NN * NN)   // e-stride in output

// Scratch (static device arrays: allocation-free)
__device__ __align__(16) float g_sup[En * NN * NN];      // relu(supports + adaptive)  (2 MB)
__device__ __align__(16) float g_nodesT[Bn * NN * Tt];   // normalized nodes, [b][n][t] (1.5 MB)
__device__ __align__(16) float g_nodesN[Bn * Tt * NN];   // normalized nodes, [b][t][n] (1.5 MB)

typedef unsigned long long ull;

// ---------------- packed f32x2 + MUFU helpers ----------------
__device__ __forceinline__ ull pack2(float a, float b) {
    ull r;
    asm("mov.b64 %0, {%1, %2};" : "=l"(r) : "f"(a), "f"(b));
    return r;
}
__device__ __forceinline__ void unpack2(ull p, float& a, float& b) {
    asm("mov.b64 {%0, %1}, %2;" : "=f"(a), "=f"(b) : "l"(p));
}
__device__ __forceinline__ ull fma2_(ull a, ull b, ull c) {
    ull d;
    asm("fma.rn.f32x2 %0, %1, %2, %3;" : "=l"(d) : "l"(a), "l"(b), "l"(c));
    return d;
}
__device__ __forceinline__ ull mul2_(ull a, ull b) {
    ull d;
    asm("mul.rn.f32x2 %0, %1, %2;" : "=l"(d) : "l"(a), "l"(b));
    return d;
}
__device__ __forceinline__ ull add2_(ull a, ull b) {
    ull d;
    asm("add.rn.f32x2 %0, %1, %2;" : "=l"(d) : "l"(a), "l"(b));
    return d;
}
__device__ __forceinline__ float sqrt_ap(float x) { float r; asm("sqrt.approx.f32 %0, %1;" : "=f"(r) : "f"(x)); return r; }
__device__ __forceinline__ float ex2_neg(float x) { float r; asm("ex2.approx.f32 %0, %1;"  : "=f"(r) : "f"(-x)); return r; }
__device__ __forceinline__ float rcp_ap(float x)  { float r; asm("rcp.approx.f32 %0, %1;"  : "=f"(r) : "f"(x)); return r; }
__device__ __forceinline__ float hadd2(ull p) {
    float a, b; unpack2(p, a, b); return a + b;
}
__device__ __forceinline__ ull shfl_xor64(ull v, int o) {
    unsigned lo = (unsigned)v, hi = (unsigned)(v >> 32);
    lo = __shfl_xor_sync(0xffffffffu, lo, o);
    hi = __shfl_xor_sync(0xffffffffu, hi, o);
    return ((ull)hi << 32) | lo;
}

// ---------------------------------------------------------------------------
// Kernel A (fused prep), 512 threads:
//   z = 0,1 : g_sup[e] = relu(supports + u * diag(s*softplus(bias)) * v^T)
//   z = 2   : L2-normalize node histories -> g_nodesT [b][n][t] + g_nodesN [b][t][n]
// ---------------------------------------------------------------------------
__global__ void __launch_bounds__(512) prep_kernel(const float* __restrict__ supports,
                                                   const float* __restrict__ u,
                                                   const float* __restrict__ s,
                                                   const float* __restrict__ v,
                                                   const float* __restrict__ bias,
                                                   const float* __restrict__ inputs) {
    const int tid = threadIdx.x;

    if (blockIdx.z == 2) {
        const int i = (blockIdx.y * 8 + blockIdx.x) * 512 + tid;  // b*512 + n
        const int b = i >> 9, n = i & (NN - 1);
        float x[Tt];
        float ss = 0.f;
        #pragma unroll
        for (int t = 0; t < Tt; t++) {
            x[t] = inputs[(((b * Tt + t) * NN) + n) * 2];
            ss = fmaf(x[t], x[t], ss);
        }
        float inv = 1.0f / fmaxf(sqrtf(ss), 1e-12f);
        #pragma unroll
        for (int t = 0; t < Tt; t++) x[t] *= inv;
        float* dst = g_nodesT + (b * NN + n) * Tt;
        *(float4*)(dst)     = make_float4(x[0], x[1], x[2],  x[3]);
        *(float4*)(dst + 4) = make_float4(x[4], x[5], x[6],  x[7]);
        *(float4*)(dst + 8) = make_float4(x[8], x[9], x[10], x[11]);
        #pragma unroll
        for (int t = 0; t < Tt; t++)
            g_nodesN[(b * Tt + t) * NN + n] = x[t];
        return;
    }

    __shared__ float su_t[Kk][68];
    __shared__ float sv_t[Kk][68];
    __shared__ float ssc[Kk];

    const int e  = blockIdx.z;
    const int n0 = blockIdx.y * 64;
    const int m0 = blockIdx.x * 64;

    if (tid < 64) {
        float bx = bias[e * Kk + tid];
        float sp = (bx > 20.f) ? bx : log1pf(__expf(bx));   // softplus
        ssc[tid] = s[e * Kk + tid] * sp;
    }
    __syncthreads();

    #pragma unroll
    for (int j = 0; j < 2; j++) {
        int idx = tid + j * 512;
        int row = idx & 63;
        int kq  = idx >> 6;
        float4 uv = *(const float4*)(u + (e * NN + n0 + row) * Kk + kq * 4);
        float4 vv = *(const float4*)(v + (e * NN + m0 + row) * Kk + kq * 4);
        su_t[kq * 4 + 0][row] = uv.x * ssc[kq * 4 + 0];
        su_t[kq * 4 + 1][row] = uv.y * ssc[kq * 4 + 1];
        su_t[kq * 4 + 2][row] = uv.z * ssc[kq * 4 + 2];
        su_t[kq * 4 + 3][row] = uv.w * ssc[kq * 4 + 3];
        sv_t[kq * 4 + 0][row] = vv.x;
        sv_t[kq * 4 + 1][row] = vv.y;
        sv_t[kq * 4 + 2][row] = vv.z;
        sv_t[kq * 4 + 3][row] = vv.w;
    }
    __syncthreads();

    const int ry = (tid >> 4) << 1;
    const int rx = (tid & 15) << 2;
    float acc[2][4] = {};

    #pragma unroll
    for (int k = 0; k < 64; k++) {
        float2 a  = *(const float2*)&su_t[k][ry];
        float4 bq = *(const float4*)&sv_t[k][rx];
        acc[0][0] = fmaf(a.x, bq.x, acc[0][0]); acc[0][1] = fmaf(a.x, bq.y, acc[0][1]);
        acc[0][2] = fmaf(a.x, bq.z, acc[0][2]); acc[0][3] = fmaf(a.x, bq.w, acc[0][3]);
        acc[1][0] = fmaf(a.y, bq.x, acc[1][0]); acc[1][1] = fmaf(a.y, bq.y, acc[1][1]);
        acc[1][2] = fmaf(a.y, bq.z, acc[1][2]); acc[1][3] = fmaf(a.y, bq.w, acc[1][3]);
    }

    #pragma unroll
    for (int i = 0; i < 2; i++) {
        int base = (e * NN + n0 + ry + i) * NN + m0 + rx;
        float4 sp = *(const float4*)(supports + base);
        float4 o;
        o.x = fmaxf(sp.x + acc[i][0], 0.f);
        o.y = fmaxf(sp.y + acc[i][1], 0.f);
        o.z = fmaxf(sp.z + acc[i][2], 0.f);
        o.w = fmaxf(sp.w + acc[i][3], 0.f);
        *(float4*)(g_sup + base) = o;
    }
}

// ---------------------------------------------------------------------------
// Kernel C: fused main pass (R8 structure, register-dieted for 4 blocks/SM).
// RN=4 rows x BOTH experts; fp-only across pipeline (val recomputed at
// writeout); T split into two 6-term halves with packed accumulators;
// xd staged once for all batches; 2 barriers/batch; invs pre-dup {iv,iv}.
// ---------------------------------------------------------------------------
__global__ void __launch_bounds__(256, 4)
main_kernel(float* __restrict__ out) {
    __shared__ ull ps[RN][256];                  // packed {e0,e1} partials, 8 KB
    __shared__ ull xd[BG * RN * Tt];             // packed {xn,xn}, all batches
    __shared__ ull invs0[2][RN];                 // {iv_e0, iv_e0}, dbl-buffered
    __shared__ ull invs1[2][RN];                 // {iv_e1, iv_e1}, dbl-buffered

    // PDL: gate on prep_kernel's writes
    cudaGridDependencySynchronize();

    const int tid  = threadIdx.x;
    const int lane = tid & 31;
    const int warp = tid >> 5;
    const int n0 = blockIdx.x * RN;
    const int b0 = blockIdx.y * BG;
    const int m0 = tid * 2;

    // sup (relu'd) in registers: batch-invariant, this thread's m-pair, both e
    ull sup0[RN], sup1[RN];
    #pragma unroll
    for (int r = 0; r < RN; r++) {
        sup0[r] = *(const ull*)(g_sup + (n0 + r) * NN + m0);
        sup1[r] = *(const ull*)(g_sup + NN * NN + (n0 + r) * NN + m0);
    }

    // Stage duplicated row-node tables for ALL batches (192 entries)
    if (tid < BG * RN * Tt) {
        int bl  = tid / (RN * Tt);
        int rem = tid - bl * (RN * Tt);
        int r = rem / Tt, t = rem - r * Tt;
        float xv = g_nodesT[(b0 + bl) * (NN * Tt) + (n0 + r) * Tt + t];
        xd[tid] = pack2(xv, xv);
    }
    __syncthreads();

    // 2 * (ln2^-1)^2
    const float C = 4.1627379620112154f;
    const ull CM = pack2(-C, -C);
    const ull CP = pack2( C,  C);

    ull fp[RN];   // packed distance factor per row (carried to next iteration)

    for (int bi = 0; bi < BG; ++bi) {
        const ull* xb = (const ull*)(g_nodesN + (b0 + bi) * (Tt * NN)) + tid;

        // 1a) first half of xm2 (t = 0..5), 6 coalesced LDG.64
        ull xm2[6];
        #pragma unroll
        for (int t = 0; t < 6; t++)
            xm2[t] = xb[t * (NN / 2)];

        // 2) previous batch's writeout in the LDG shadow (val recomputed)
        if (bi > 0) {
            const int pv = (bi - 1) & 1;
            float* ob = out + ((b0 + bi - 1) * NN + n0) * NN + m0;
            #pragma unroll
            for (int r = 0; r < RN; r++) {
                *(ull*)(ob + r * NN)        = mul2_(mul2_(fp[r], sup0[r]), invs0[pv][r]);
                *(ull*)(ob + ESTR + r * NN) = mul2_(mul2_(fp[r], sup1[r]), invs1[pv][r]);
            }
        }

        // 3a) first-half partial inner products (packed acc per row)
        ull acc[RN];
        #pragma unroll
        for (int r = 0; r < RN; r++) {
            const ulonglong2* xdp = (const ulonglong2*)&xd[(bi * RN + r) * Tt];
            ulonglong2 q0 = xdp[0], q1 = xdp[1], q2 = xdp[2];
            ull pa = mul2_(xm2[0], q0.x);
            ull pb = mul2_(xm2[1], q0.y);
            pa = fma2_(xm2[2], q1.x, pa);  pb = fma2_(xm2[3], q1.y, pb);
            pa = fma2_(xm2[4], q2.x, pa);  pb = fma2_(xm2[5], q2.y, pb);
            acc[r] = add2_(pa, pb);
        }

        // 1b) second half of xm2 (t = 6..11) reusing registers
        #pragma unroll
        for (int t = 0; t < 6; t++)
            xm2[t] = xb[(t + 6) * (NN / 2)];

        // 3b) second-half accumulate + factor + packed partial sums
        #pragma unroll
        for (int r = 0; r < RN; r++) {
            const ulonglong2* xdp = (const ulonglong2*)&xd[(bi * RN + r) * Tt] + 3;
            ulonglong2 q3 = xdp[0], q4 = xdp[1], q5 = xdp[2];
            ull pa = mul2_(xm2[0], q3.x);
            ull pb = mul2_(xm2[1], q3.y);
            pa = fma2_(xm2[2], q4.x, pa);  pb = fma2_(xm2[3], q4.y, pb);
            pa = fma2_(xm2[4], q5.x, pa);  pb = fma2_(xm2[5], q5.y, pb);
            ull inner2 = add2_(acc[r], add2_(pa, pb));

            ull d2p = fma2_(inner2, CM, CP);  // (1.4427*d)^2 packed
            float d20, d21;
            unpack2(d2p, d20, d21);
            d20 = fmaxf(d20, 0.f);
            d21 = fmaxf(d21, 0.f);
            float f0 = ex2_neg(sqrt_ap(d20)) + 1.0f;
            float f1 = ex2_neg(sqrt_ap(d21)) + 1.0f;
            fp[r] = pack2(f0, f1);

            ps[r][tid] = pack2(hadd2(mul2_(fp[r], sup0[r])),
                               hadd2(mul2_(fp[r], sup1[r])));
        }
        __syncthreads();   // ps ready

        // 4) packed reduction: warps 0..RN-1 each reduce one row (256 ulls)
        if (warp < RN) {
            const ulonglong2* p = (const ulonglong2*)ps[warp];
            ulonglong2 a0 = p[lane];
            ulonglong2 a1 = p[lane + 32];
            ulonglong2 a2 = p[lane + 64];
            ulonglong2 a3 = p[lane + 96];
            ull s01 = add2_(add2_(a0.x, a0.y), add2_(a1.x, a1.y));
            ull s23 = add2_(add2_(a2.x, a2.y), add2_(a3.x, a3.y));
            ull sum = add2_(s01, s23);
            #pragma unroll
            for (int o = 16; o > 0; o >>= 1)
                sum = add2_(sum, shfl_xor64(sum, o));
            if (lane == 0) {
                float s0, s1;
                unpack2(sum, s0, s1);
                float i0 = rcp_ap(fmaxf(s0, 1e-12f));
                float i1 = rcp_ap(fmaxf(s1, 1e-12f));
                invs0[bi & 1][warp] = pack2(i0, i0);
                invs1[bi & 1][warp] = pack2(i1, i1);
            }
        }
        __syncthreads();   // invs ready; guards ps reuse next iter
    }

    // Epilogue: last batch's writeout
    {
        const int pv = (BG - 1) & 1;
        float* ob = out + ((b0 + BG - 1) * NN + n0) * NN + m0;
        #pragma unroll
        for (int r = 0; r < RN; r++) {
            *(ull*)(ob + r * NN)        = mul2_(mul2_(fp[r], sup0[r]), invs0[pv][r]);
            *(ull*)(ob + ESTR + r * NN) = mul2_(mul2_(fp[r], sup1[r]), invs1[pv][r]);
        }
    }
}

// ---------------------------------------------------------------------------
extern "C" void kernel_launch(void* const* d_in, const int* in_sizes, int n_in,
                              void* d_out, int out_size) {
    const float* supports = (const float*)d_in[0];  // [2,512,512]
    const float* u        = (const float*)d_in[1];  // [2,512,64]
    const float* s        = (const float*)d_in[2];  // [2,64]
    const float* v        = (const float*)d_in[3];  // [2,512,64]
    const float* bias     = (const float*)d_in[4];  // [2,64]
    const float* inputs   = (const float*)d_in[5];  // [64,12,512,2]
    float* out = (float*)d_out;                     // [2,64,512,512]

    prep_kernel<<<dim3(8, 8, 3), 512>>>(supports, u, s, v, bias, inputs);

    // PDL launch: main may ramp while prep drains; in-kernel
    // cudaGridDependencySynchronize() gates consumption of prep outputs.
    cudaLaunchConfig_t cfg = {};
    cfg.gridDim  = dim3(NN / RN, Bn / BG);
    cfg.blockDim = dim3(256);
    cudaLaunchAttribute attr[1];
    attr[0].id = cudaLaunchAttributeProgrammaticStreamSerialization;
    attr[0].val.programmaticStreamSerializationAllowed = 1;
    cfg.attrs = attr;
    cfg.numAttrs = 1;
    cudaLaunchKernelEx(&cfg, main_kernel, out);
}

// round 14
// speedup vs baseline: 1.0011x; 1.0011x over previous
#include <cuda_runtime.h>
#include <math.h>

#define En 2
#define NN 512
#define Bn 64
#define Tt 12
#define Kk 64
#define RN 4     // rows per block tile in main kernel
#define BG 4     // batches per block (2 super-iterations x 2)
#define ESTR (Bn * NN * NN)   // e-stride in output

// Scratch (static device arrays: allocation-free)
__device__ __align__(16) float g_sup[En * NN * NN];      // relu(supports + adaptive)  (2 MB)
__device__ __align__(16) float g_nodesT[Bn * NN * Tt];   // normalized nodes, [b][n][t] (1.5 MB)
__device__ __align__(16) float g_nodesN[Bn * Tt * NN];   // normalized nodes, [b][t][n] (1.5 MB)

typedef unsigned long long ull;

// ---------------- packed f32x2 + MUFU helpers ----------------
__device__ __forceinline__ ull pack2(float a, float b) {
    ull r;
    asm("mov.b64 %0, {%1, %2};" : "=l"(r) : "f"(a), "f"(b));
    return r;
}
__device__ __forceinline__ void unpack2(ull p, float& a, float& b) {
    asm("mov.b64 {%0, %1}, %2;" : "=f"(a), "=f"(b) : "l"(p));
}
__device__ __forceinline__ ull fma2_(ull a, ull b, ull c) {
    ull d;
    asm("fma.rn.f32x2 %0, %1, %2, %3;" : "=l"(d) : "l"(a), "l"(b), "l"(c));
    return d;
}
__device__ __forceinline__ ull mul2_(ull a, ull b) {
    ull d;
    asm("mul.rn.f32x2 %0, %1, %2;" : "=l"(d) : "l"(a), "l"(b));
    return d;
}
__device__ __forceinline__ ull add2_(ull a, ull b) {
    ull d;
    asm("add.rn.f32x2 %0, %1, %2;" : "=l"(d) : "l"(a), "l"(b));
    return d;
}
__device__ __forceinline__ float sqrt_ap(float x) { float r; asm("sqrt.approx.f32 %0, %1;" : "=f"(r) : "f"(x)); return r; }
__device__ __forceinline__ float ex2_neg(float x) { float r; asm("ex2.approx.f32 %0, %1;"  : "=f"(r) : "f"(-x)); return r; }
__device__ __forceinline__ float rcp_ap(float x)  { float r; asm("rcp.approx.f32 %0, %1;"  : "=f"(r) : "f"(x)); return r; }
__device__ __forceinline__ float hadd2(ull p) {
    float a, b; unpack2(p, a, b); return a + b;
}
__device__ __forceinline__ ull shfl_xor64(ull v, int o) {
    unsigned lo = (unsigned)v, hi = (unsigned)(v >> 32);
    lo = __shfl_xor_sync(0xffffffffu, lo, o);
    hi = __shfl_xor_sync(0xffffffffu, hi, o);
    return ((ull)hi << 32) | lo;
}

// ---------------------------------------------------------------------------
// Kernel A (fused prep), 512 threads:
//   z = 0,1 : g_sup[e] = relu(supports + u * diag(s*softplus(bias)) * v^T)
//   z = 2   : L2-normalize node histories -> g_nodesT [b][n][t] + g_nodesN [b][t][n]
// ---------------------------------------------------------------------------
__global__ void __launch_bounds__(512) prep_kernel(const float* __restrict__ supports,
                                                   const float* __restrict__ u,
                                                   const float* __restrict__ s,
                                                   const float* __restrict__ v,
                                                   const float* __restrict__ bias,
                                                   const float* __restrict__ inputs) {
    const int tid = threadIdx.x;

    if (blockIdx.z == 2) {
        const int i = (blockIdx.y * 8 + blockIdx.x) * 512 + tid;  // b*512 + n
        const int b = i >> 9, n = i & (NN - 1);
        float x[Tt];
        float ss = 0.f;
        #pragma unroll
        for (int t = 0; t < Tt; t++) {
            x[t] = inputs[(((b * Tt + t) * NN) + n) * 2];
            ss = fmaf(x[t], x[t], ss);
        }
        float inv = 1.0f / fmaxf(sqrtf(ss), 1e-12f);
        #pragma unroll
        for (int t = 0; t < Tt; t++) x[t] *= inv;
        float* dst = g_nodesT + (b * NN + n) * Tt;
        *(float4*)(dst)     = make_float4(x[0], x[1], x[2],  x[3]);
        *(float4*)(dst + 4) = make_float4(x[4], x[5], x[6],  x[7]);
        *(float4*)(dst + 8) = make_float4(x[8], x[9], x[10], x[11]);
        #pragma unroll
        for (int t = 0; t < Tt; t++)
            g_nodesN[(b * Tt + t) * NN + n] = x[t];
        return;
    }

    __shared__ float su_t[Kk][68];
    __shared__ float sv_t[Kk][68];
    __shared__ float ssc[Kk];

    const int e  = blockIdx.z;
    const int n0 = blockIdx.y * 64;
    const int m0 = blockIdx.x * 64;

    if (tid < 64) {
        float bx = bias[e * Kk + tid];
        float sp = (bx > 20.f) ? bx : log1pf(__expf(bx));   // softplus
        ssc[tid] = s[e * Kk + tid] * sp;
    }
    __syncthreads();

    #pragma unroll
    for (int j = 0; j < 2; j++) {
        int idx = tid + j * 512;
        int row = idx & 63;
        int kq  = idx >> 6;
        float4 uv = *(const float4*)(u + (e * NN + n0 + row) * Kk + kq * 4);
        float4 vv = *(const float4*)(v + (e * NN + m0 + row) * Kk + kq * 4);
        su_t[kq * 4 + 0][row] = uv.x * ssc[kq * 4 + 0];
        su_t[kq * 4 + 1][row] = uv.y * ssc[kq * 4 + 1];
        su_t[kq * 4 + 2][row] = uv.z * ssc[kq * 4 + 2];
        su_t[kq * 4 + 3][row] = uv.w * ssc[kq * 4 + 3];
        sv_t[kq * 4 + 0][row] = vv.x;
        sv_t[kq * 4 + 1][row] = vv.y;
        sv_t[kq * 4 + 2][row] = vv.z;
        sv_t[kq * 4 + 3][row] = vv.w;
    }
    __syncthreads();

    const int ry = (tid >> 4) << 1;
    const int rx = (tid & 15) << 2;
    float acc[2][4] = {};

    #pragma unroll
    for (int k = 0; k < 64; k++) {
        float2 a  = *(const float2*)&su_t[k][ry];
        float4 bq = *(const float4*)&sv_t[k][rx];
        acc[0][0] = fmaf(a.x, bq.x, acc[0][0]); acc[0][1] = fmaf(a.x, bq.y, acc[0][1]);
        acc[0][2] = fmaf(a.x, bq.z, acc[0][2]); acc[0][3] = fmaf(a.x, bq.w, acc[0][3]);
        acc[1][0] = fmaf(a.y, bq.x, acc[1][0]); acc[1][1] = fmaf(a.y, bq.y, acc[1][1]);
        acc[1][2] = fmaf(a.y, bq.z, acc[1][2]); acc[1][3] = fmaf(a.y, bq.w, acc[1][3]);
    }

    #pragma unroll
    for (int i = 0; i < 2; i++) {
        int base = (e * NN + n0 + ry + i) * NN + m0 + rx;
        float4 sp = *(const float4*)(supports + base);
        float4 o;
        o.x = fmaxf(sp.x + acc[i][0], 0.f);
        o.y = fmaxf(sp.y + acc[i][1], 0.f);
        o.z = fmaxf(sp.z + acc[i][2], 0.f);
        o.w = fmaxf(sp.w + acc[i][3], 0.f);
        *(float4*)(g_sup + base) = o;
    }
}

// ---------------------------------------------------------------------------
// Kernel C: fused main pass — 2 batches per super-iteration.
// 24 xm2 LDGs issued together (MLP); single barrier pair per 2 batches;
// all 8 warps reduce in parallel (2 batches x 4 rows = 8 sums).
// ---------------------------------------------------------------------------
__global__ void __launch_bounds__(256, 2)
main_kernel(float* __restrict__ out) {
    __shared__ ull ps[2][RN][256];               // [batchInPair][row][tid], 16 KB
    __shared__ ull xd[BG * RN * Tt];             // packed {xn,xn}, all batches
    __shared__ ull invs0[2][2][RN];              // [parity][bp][row] {iv,iv} e0
    __shared__ ull invs1[2][2][RN];              // [parity][bp][row] {iv,iv} e1

    // PDL: gate on prep_kernel's writes
    cudaGridDependencySynchronize();

    const int tid  = threadIdx.x;
    const int lane = tid & 31;
    const int warp = tid >> 5;
    const int n0 = blockIdx.x * RN;
    const int b0 = blockIdx.y * BG;
    const int m0 = tid * 2;

    // sup (relu'd) in registers: batch-invariant, this thread's m-pair, both e
    ull sup0[RN], sup1[RN];
    #pragma unroll
    for (int r = 0; r < RN; r++) {
        sup0[r] = *(const ull*)(g_sup + (n0 + r) * NN + m0);
        sup1[r] = *(const ull*)(g_sup + NN * NN + (n0 + r) * NN + m0);
    }

    // Stage duplicated row-node tables for ALL batches (192 entries)
    if (tid < BG * RN * Tt) {
        int bl  = tid / (RN * Tt);
        int rem = tid - bl * (RN * Tt);
        int r = rem / Tt, t = rem - r * Tt;
        float xv = g_nodesT[(b0 + bl) * (NN * Tt) + (n0 + r) * Tt + t];
        xd[tid] = pack2(xv, xv);
    }
    __syncthreads();

    // 2 * (ln2^-1)^2
    const float C = 4.1627379620112154f;
    const ull CM = pack2(-C, -C);
    const ull CP = pack2( C,  C);

    ull fpa[RN], fpb[RN];   // packed distance factors for the 2 in-flight batches

    #pragma unroll
    for (int si = 0; si < BG / 2; ++si) {
        const int ba = b0 + 2 * si;       // batch a
        // 1) both batches' xm2 loads issued together (24 coalesced LDG.64)
        ull xm2a[Tt], xm2b[Tt];
        {
            const ull* xa = (const ull*)(g_nodesN + ba * (Tt * NN)) + tid;
            const ull* xb = xa + (Tt * NN) / 2;
            #pragma unroll
            for (int t = 0; t < Tt; t++) xm2a[t] = xa[t * (NN / 2)];
            #pragma unroll
            for (int t = 0; t < Tt; t++) xm2b[t] = xb[t * (NN / 2)];
        }

        // 2) previous super-iteration's writeout in the LDG shadow
        if (si > 0) {
            const int pv = (si - 1) & 1;
            float* oa = out + ((ba - 2) * NN + n0) * NN + m0;
            #pragma unroll
            for (int r = 0; r < RN; r++) {
                *(ull*)(oa + r * NN)             = mul2_(mul2_(fpa[r], sup0[r]), invs0[pv][0][r]);
                *(ull*)(oa + ESTR + r * NN)      = mul2_(mul2_(fpa[r], sup1[r]), invs1[pv][0][r]);
                *(ull*)(oa + NN * NN + r * NN)   = mul2_(mul2_(fpb[r], sup0[r]), invs0[pv][1][r]);
                *(ull*)(oa + NN * NN + ESTR + r * NN)
                                                 = mul2_(mul2_(fpb[r], sup1[r]), invs1[pv][1][r]);
            }
        }

        // 3) compute both batches' distance factors + packed partial sums
        #pragma unroll
        for (int r = 0; r < RN; r++) {
            const ulonglong2* xda = (const ulonglong2*)&xd[(2 * si * RN + r) * Tt];
            ulonglong2 q0 = xda[0], q1 = xda[1], q2 = xda[2];
            ulonglong2 q3 = xda[3], q4 = xda[4], q5 = xda[5];
            ull pa = mul2_(xm2a[0], q0.x);
            ull pb = mul2_(xm2a[1], q0.y);
            pa = fma2_(xm2a[2],  q1.x, pa);  pb = fma2_(xm2a[3],  q1.y, pb);
            pa = fma2_(xm2a[4],  q2.x, pa);  pb = fma2_(xm2a[5],  q2.y, pb);
            pa = fma2_(xm2a[6],  q3.x, pa);  pb = fma2_(xm2a[7],  q3.y, pb);
            pa = fma2_(xm2a[8],  q4.x, pa);  pb = fma2_(xm2a[9],  q4.y, pb);
            pa = fma2_(xm2a[10], q5.x, pa);  pb = fma2_(xm2a[11], q5.y, pb);
            ull d2p = fma2_(add2_(pa, pb), CM, CP);
            float d20, d21;
            unpack2(d2p, d20, d21);
            d20 = fmaxf(d20, 0.f);
            d21 = fmaxf(d21, 0.f);
            float f0 = ex2_neg(sqrt_ap(d20)) + 1.0f;
            float f1 = ex2_neg(sqrt_ap(d21)) + 1.0f;
            fpa[r] = pack2(f0, f1);
            ps[0][r][tid] = pack2(hadd2(mul2_(fpa[r], sup0[r])),
                                  hadd2(mul2_(fpa[r], sup1[r])));
        }
        #pragma unroll
        for (int r = 0; r < RN; r++) {
            const ulonglong2* xdb = (const ulonglong2*)&xd[((2 * si + 1) * RN + r) * Tt];
            ulonglong2 q0 = xdb[0], q1 = xdb[1], q2 = xdb[2];
            ulonglong2 q3 = xdb[3], q4 = xdb[4], q5 = xdb[5];
            ull pa = mul2_(xm2b[0], q0.x);
            ull pb = mul2_(xm2b[1], q0.y);
            pa = fma2_(xm2b[2],  q1.x, pa);  pb = fma2_(xm2b[3],  q1.y, pb);
            pa = fma2_(xm2b[4],  q2.x, pa);  pb = fma2_(xm2b[5],  q2.y, pb);
            pa = fma2_(xm2b[6],  q3.x, pa);  pb = fma2_(xm2b[7],  q3.y, pb);
            pa = fma2_(xm2b[8],  q4.x, pa);  pb = fma2_(xm2b[9],  q4.y, pb);
            pa = fma2_(xm2b[10], q5.x, pa);  pb = fma2_(xm2b[11], q5.y, pb);
            ull d2p = fma2_(add2_(pa, pb), CM, CP);
            float d20, d21;
            unpack2(d2p, d20, d21);
            d20 = fmaxf(d20, 0.f);
            d21 = fmaxf(d21, 0.f);
            float f0 = ex2_neg(sqrt_ap(d20)) + 1.0f;
            float f1 = ex2_neg(sqrt_ap(d21)) + 1.0f;
            fpb[r] = pack2(f0, f1);
            ps[1][r][tid] = pack2(hadd2(mul2_(fpb[r], sup0[r])),
                                  hadd2(mul2_(fpb[r], sup1[r])));
        }
        __syncthreads();   // ps (both batches) ready

        // 4) ALL 8 warps reduce: warp w -> batchInPair w>>2, row w&3
        {
            const int bp = warp >> 2;
            const int rw = warp & 3;
            const ulonglong2* p = (const ulonglong2*)ps[bp][rw];
            ulonglong2 a0 = p[lane];
            ulonglong2 a1 = p[lane + 32];
            ulonglong2 a2 = p[lane + 64];
            ulonglong2 a3 = p[lane + 96];
            ull s01 = add2_(add2_(a0.x, a0.y), add2_(a1.x, a1.y));
            ull s23 = add2_(add2_(a2.x, a2.y), add2_(a3.x, a3.y));
            ull sum = add2_(s01, s23);
            #pragma unroll
            for (int o = 16; o > 0; o >>= 1)
                sum = add2_(sum, shfl_xor64(sum, o));
            if (lane == 0) {
                float s0, s1;
                unpack2(sum, s0, s1);
                float i0 = rcp_ap(fmaxf(s0, 1e-12f));
                float i1 = rcp_ap(fmaxf(s1, 1e-12f));
                invs0[si & 1][bp][rw] = pack2(i0, i0);
                invs1[si & 1][bp][rw] = pack2(i1, i1);
            }
        }
        __syncthreads();   // invs ready; guards ps reuse next super-iter
    }

    // Epilogue: last super-iteration's writeout (batches b0+2, b0+3)
    {
        const int pv = (BG / 2 - 1) & 1;
        float* oa = out + ((b0 + BG - 2) * NN + n0) * NN + m0;
        #pragma unroll
        for (int r = 0; r < RN; r++) {
            *(ull*)(oa + r * NN)             = mul2_(mul2_(fpa[r], sup0[r]), invs0[pv][0][r]);
            *(ull*)(oa + ESTR + r * NN)      = mul2_(mul2_(fpa[r], sup1[r]), invs1[pv][0][r]);
            *(ull*)(oa + NN * NN + r * NN)   = mul2_(mul2_(fpb[r], sup0[r]), invs0[pv][1][r]);
            *(ull*)(oa + NN * NN + ESTR + r * NN)
                                             = mul2_(mul2_(fpb[r], sup1[r]), invs1[pv][1][r]);
        }
    }
}

// ---------------------------------------------------------------------------
extern "C" void kernel_launch(void* const* d_in, const int* in_sizes, int n_in,
                              void* d_out, int out_size) {
    const float* supports = (const float*)d_in[0];  // [2,512,512]
    const float* u        = (const float*)d_in[1];  // [2,512,64]
    const float* s        = (const float*)d_in[2];  // [2,64]
    const float* v        = (const float*)d_in[3];  // [2,512,64]
    const float* bias     = (const float*)d_in[4];  // [2,64]
    const float* inputs   = (const float*)d_in[5];  // [64,12,512,2]
    float* out = (float*)d_out;                     // [2,64,512,512]

    prep_kernel<<<dim3(8, 8, 3), 512>>>(supports, u, s, v, bias, inputs);

    // PDL launch: main may ramp while prep drains.
    cudaLaunchConfig_t cfg = {};
    cfg.gridDim  = dim3(NN / RN, Bn / BG);
    cfg.blockDim = dim3(256);
    cudaLaunchAttribute attr[1];
    attr[0].id = cudaLaunchAttributeProgrammaticStreamSerialization;
    attr[0].val.programmaticStreamSerializationAllowed = 1;
    cfg.attrs = attr;
    cfg.numAttrs = 1;
    cudaLaunchKernelEx(&cfg, main_kernel, out);
}

// round 15
// speedup vs baseline: 1.0754x; 1.0743x over previous
#include <cuda_runtime.h>
#include <math.h>

#define En 2
#define NN 512
#define Bn 64
#define Tt 12
#define Kk 64
#define RN 4     // rows per block tile in main kernel
#define BG 4     // batches per block in main kernel
#define ESTR (Bn * NN * NN)   // e-stride in output

// Scratch (static device arrays: allocation-free)
__device__ __align__(16) float g_sup[En * NN * NN];      // relu(supports + adaptive)  (2 MB)
__device__ __align__(16) float g_nodesT[Bn * NN * Tt];   // normalized nodes, [b][n][t] (1.5 MB)
__device__ __align__(16) float g_nodesN[Bn * Tt * NN];   // normalized nodes, [b][t][n] (1.5 MB)

typedef unsigned long long ull;

// ---------------- packed f32x2 + MUFU helpers ----------------
__device__ __forceinline__ ull pack2(float a, float b) {
    ull r;
    asm("mov.b64 %0, {%1, %2};" : "=l"(r) : "f"(a), "f"(b));
    return r;
}
__device__ __forceinline__ void unpack2(ull p, float& a, float& b) {
    asm("mov.b64 {%0, %1}, %2;" : "=f"(a), "=f"(b) : "l"(p));
}
__device__ __forceinline__ ull fma2_(ull a, ull b, ull c) {
    ull d;
    asm("fma.rn.f32x2 %0, %1, %2, %3;" : "=l"(d) : "l"(a), "l"(b), "l"(c));
    return d;
}
__device__ __forceinline__ ull mul2_(ull a, ull b) {
    ull d;
    asm("mul.rn.f32x2 %0, %1, %2;" : "=l"(d) : "l"(a), "l"(b));
    return d;
}
__device__ __forceinline__ ull add2_(ull a, ull b) {
    ull d;
    asm("add.rn.f32x2 %0, %1, %2;" : "=l"(d) : "l"(a), "l"(b));
    return d;
}
__device__ __forceinline__ float sqrt_ap(float x) { float r; asm("sqrt.approx.f32 %0, %1;" : "=f"(r) : "f"(x)); return r; }
__device__ __forceinline__ float ex2_neg(float x) { float r; asm("ex2.approx.f32 %0, %1;"  : "=f"(r) : "f"(-x)); return r; }
__device__ __forceinline__ float rcp_ap(float x)  { float r; asm("rcp.approx.f32 %0, %1;"  : "=f"(r) : "f"(x)); return r; }
__device__ __forceinline__ float hadd2(ull p) {
    float a, b; unpack2(p, a, b); return a + b;
}
__device__ __forceinline__ ull shfl_xor64(ull v, int o) {
    unsigned lo = (unsigned)v, hi = (unsigned)(v >> 32);
    lo = __shfl_xor_sync(0xffffffffu, lo, o);
    hi = __shfl_xor_sync(0xffffffffu, hi, o);
    return ((ull)hi << 32) | lo;
}

// ---------------------------------------------------------------------------
// Kernel A (fused prep), 512 threads:
//   z = 0,1 : g_sup[e] = relu(supports + u * diag(s*softplus(bias)) * v^T)
//   z = 2   : L2-normalize node histories -> g_nodesT [b][n][t] + g_nodesN [b][t][n]
// ---------------------------------------------------------------------------
__global__ void __launch_bounds__(512) prep_kernel(const float* __restrict__ supports,
                                                   const float* __restrict__ u,
                                                   const float* __restrict__ s,
                                                   const float* __restrict__ v,
                                                   const float* __restrict__ bias,
                                                   const float* __restrict__ inputs) {
    const int tid = threadIdx.x;

    if (blockIdx.z == 2) {
        const int i = (blockIdx.y * 8 + blockIdx.x) * 512 + tid;  // b*512 + n
        const int b = i >> 9, n = i & (NN - 1);
        float x[Tt];
        float ss = 0.f;
        #pragma unroll
        for (int t = 0; t < Tt; t++) {
            x[t] = inputs[(((b * Tt + t) * NN) + n) * 2];
            ss = fmaf(x[t], x[t], ss);
        }
        float inv = 1.0f / fmaxf(sqrtf(ss), 1e-12f);
        #pragma unroll
        for (int t = 0; t < Tt; t++) x[t] *= inv;
        float* dst = g_nodesT + (b * NN + n) * Tt;
        *(float4*)(dst)     = make_float4(x[0], x[1], x[2],  x[3]);
        *(float4*)(dst + 4) = make_float4(x[4], x[5], x[6],  x[7]);
        *(float4*)(dst + 8) = make_float4(x[8], x[9], x[10], x[11]);
        #pragma unroll
        for (int t = 0; t < Tt; t++)
            g_nodesN[(b * Tt + t) * NN + n] = x[t];
        return;
    }

    __shared__ float su_t[Kk][68];
    __shared__ float sv_t[Kk][68];
    __shared__ float ssc[Kk];

    const int e  = blockIdx.z;
    const int n0 = blockIdx.y * 64;
    const int m0 = blockIdx.x * 64;

    if (tid < 64) {
        float bx = bias[e * Kk + tid];
        float sp = (bx > 20.f) ? bx : log1pf(__expf(bx));   // softplus
        ssc[tid] = s[e * Kk + tid] * sp;
    }
    __syncthreads();

    #pragma unroll
    for (int j = 0; j < 2; j++) {
        int idx = tid + j * 512;
        int row = idx & 63;
        int kq  = idx >> 6;
        float4 uv = *(const float4*)(u + (e * NN + n0 + row) * Kk + kq * 4);
        float4 vv = *(const float4*)(v + (e * NN + m0 + row) * Kk + kq * 4);
        su_t[kq * 4 + 0][row] = uv.x * ssc[kq * 4 + 0];
        su_t[kq * 4 + 1][row] = uv.y * ssc[kq * 4 + 1];
        su_t[kq * 4 + 2][row] = uv.z * ssc[kq * 4 + 2];
        su_t[kq * 4 + 3][row] = uv.w * ssc[kq * 4 + 3];
        sv_t[kq * 4 + 0][row] = vv.x;
        sv_t[kq * 4 + 1][row] = vv.y;
        sv_t[kq * 4 + 2][row] = vv.z;
        sv_t[kq * 4 + 3][row] = vv.w;
    }
    __syncthreads();

    const int ry = (tid >> 4) << 1;
    const int rx = (tid & 15) << 2;
    float acc[2][4] = {};

    #pragma unroll
    for (int k = 0; k < 64; k++) {
        float2 a  = *(const float2*)&su_t[k][ry];
        float4 bq = *(const float4*)&sv_t[k][rx];
        acc[0][0] = fmaf(a.x, bq.x, acc[0][0]); acc[0][1] = fmaf(a.x, bq.y, acc[0][1]);
        acc[0][2] = fmaf(a.x, bq.z, acc[0][2]); acc[0][3] = fmaf(a.x, bq.w, acc[0][3]);
        acc[1][0] = fmaf(a.y, bq.x, acc[1][0]); acc[1][1] = fmaf(a.y, bq.y, acc[1][1]);
        acc[1][2] = fmaf(a.y, bq.z, acc[1][2]); acc[1][3] = fmaf(a.y, bq.w, acc[1][3]);
    }

    #pragma unroll
    for (int i = 0; i < 2; i++) {
        int base = (e * NN + n0 + ry + i) * NN + m0 + rx;
        float4 sp = *(const float4*)(supports + base);
        float4 o;
        o.x = fmaxf(sp.x + acc[i][0], 0.f);
        o.y = fmaxf(sp.y + acc[i][1], 0.f);
        o.z = fmaxf(sp.z + acc[i][2], 0.f);
        o.w = fmaxf(sp.w + acc[i][3], 0.f);
        *(float4*)(g_sup + base) = o;
    }
}

// ---------------------------------------------------------------------------
// Kernel C: fused main pass, software-pipelined.
// RN=4 rows x BOTH experts per block; xd staged once for all BG batches;
// xm2 LDGs issued before prev-batch writeout (latency shadow);
// 2 barriers per batch (ps-ready, invs-ready), double-buffered invs.
// ---------------------------------------------------------------------------
__global__ void __launch_bounds__(256, 3)
main_kernel(float* __restrict__ out) {
    __shared__ ull ps[RN][256];                  // packed {e0,e1} partials, 8 KB
    __shared__ ull xd[BG * RN * Tt];             // packed {xn,xn}, all batches
    __shared__ ull invs[2][RN];                  // packed {iv_e0, iv_e1}, dbl-buffered

    const int tid  = threadIdx.x;
    const int lane = tid & 31;
    const int warp = tid >> 5;
    const int n0 = blockIdx.x * RN;
    const int b0 = blockIdx.y * BG;
    const int m0 = tid * 2;

    // sup (relu'd) in registers: batch-invariant, this thread's m-pair, both e
    ull sup0[RN], sup1[RN];
    #pragma unroll
    for (int r = 0; r < RN; r++) {
        sup0[r] = *(const ull*)(g_sup + (n0 + r) * NN + m0);
        sup1[r] = *(const ull*)(g_sup + NN * NN + (n0 + r) * NN + m0);
    }

    // Stage duplicated row-node tables for ALL batches (192 entries)
    if (tid < BG * RN * Tt) {
        int bl  = tid / (RN * Tt);
        int rem = tid - bl * (RN * Tt);
        int r = rem / Tt, t = rem - r * Tt;
        float xv = g_nodesT[(b0 + bl) * (NN * Tt) + (n0 + r) * Tt + t];
        xd[tid] = pack2(xv, xv);
    }
    __syncthreads();

    // 2 * (ln2^-1)^2
    const float C = 4.1627379620112154f;
    const ull CM = pack2(-C, -C);
    const ull CP = pack2( C,  C);

    ull val0[RN], val1[RN];

    #pragma unroll 2
    for (int bi = 0; bi < BG; ++bi) {
        // 1) issue this batch's xm2 loads FIRST (12 coalesced LDG.64)
        ull xm2[Tt];
        {
            const ull* xb = (const ull*)(g_nodesN + (b0 + bi) * (Tt * NN)) + tid;
            #pragma unroll
            for (int t = 0; t < Tt; t++)
                xm2[t] = xb[t * (NN / 2)];
        }

        // 2) previous batch's writeout in the LDG shadow
        if (bi > 0) {
            const int pv = (bi - 1) & 1;
            float* ob = out + ((b0 + bi - 1) * NN + n0) * NN + m0;
            #pragma unroll
            for (int r = 0; r < RN; r++) {
                float iv0, iv1;
                unpack2(invs[pv][r], iv0, iv1);
                *(ull*)(ob + r * NN)        = mul2_(val0[r], pack2(iv0, iv0));
                *(ull*)(ob + ESTR + r * NN) = mul2_(val1[r], pack2(iv1, iv1));
            }
        }

        // 3) compute vals + packed partial sums
        #pragma unroll
        for (int r = 0; r < RN; r++) {
            const ulonglong2* xdp = (const ulonglong2*)&xd[(bi * RN + r) * Tt];
            ulonglong2 q0 = xdp[0], q1 = xdp[1], q2 = xdp[2];
            ulonglong2 q3 = xdp[3], q4 = xdp[4], q5 = xdp[5];
            ull pa = mul2_(xm2[0], q0.x);
            ull pb = mul2_(xm2[1], q0.y);
            pa = fma2_(xm2[2],  q1.x, pa);  pb = fma2_(xm2[3],  q1.y, pb);
            pa = fma2_(xm2[4],  q2.x, pa);  pb = fma2_(xm2[5],  q2.y, pb);
            pa = fma2_(xm2[6],  q3.x, pa);  pb = fma2_(xm2[7],  q3.y, pb);
            pa = fma2_(xm2[8],  q4.x, pa);  pb = fma2_(xm2[9],  q4.y, pb);
            pa = fma2_(xm2[10], q5.x, pa);  pb = fma2_(xm2[11], q5.y, pb);
            ull inner2 = add2_(pa, pb);
            ull d2p = fma2_(inner2, CM, CP);  // (1.4427*d)^2 packed
            float d20, d21;
            unpack2(d2p, d20, d21);
            d20 = fmaxf(d20, 0.f);
            d21 = fmaxf(d21, 0.f);
            float f0 = ex2_neg(sqrt_ap(d20)) + 1.0f;
            float f1 = ex2_neg(sqrt_ap(d21)) + 1.0f;
            ull fp = pack2(f0, f1);

            val0[r] = mul2_(fp, sup0[r]);
            val1[r] = mul2_(fp, sup1[r]);
            ps[r][tid] = pack2(hadd2(val0[r]), hadd2(val1[r]));
        }
        __syncthreads();   // ps ready

        // 4) packed reduction: warps 0..RN-1 each reduce one row (256 ulls)
        if (warp < RN) {
            const ulonglong2* p = (const ulonglong2*)ps[warp];
            ulonglong2 a0 = p[lane];
            ulonglong2 a1 = p[lane + 32];
            ulonglong2 a2 = p[lane + 64];
            ulonglong2 a3 = p[lane + 96];
            ull s01 = add2_(add2_(a0.x, a0.y), add2_(a1.x, a1.y));
            ull s23 = add2_(add2_(a2.x, a2.y), add2_(a3.x, a3.y));
            ull sum = add2_(s01, s23);
            #pragma unroll
            for (int o = 16; o > 0; o >>= 1)
                sum = add2_(sum, shfl_xor64(sum, o));
            if (lane == 0) {
                float s0, s1;
                unpack2(sum, s0, s1);
                invs[bi & 1][warp] = pack2(rcp_ap(fmaxf(s0, 1e-12f)),
                                           rcp_ap(fmaxf(s1, 1e-12f)));
            }
        }
        __syncthreads();   // invs ready; guards ps reuse next iter
    }

    // Epilogue: last batch's writeout
    {
        const int pv = (BG - 1) & 1;
        float* ob = out + ((b0 + BG - 1) * NN + n0) * NN + m0;
        #pragma unroll
        for (int r = 0; r < RN; r++) {
            float iv0, iv1;
            unpack2(invs[pv][r], iv0, iv1);
            *(ull*)(ob + r * NN)        = mul2_(val0[r], pack2(iv0, iv0));
            *(ull*)(ob + ESTR + r * NN) = mul2_(val1[r], pack2(iv1, iv1));
        }
    }
}

// ---------------------------------------------------------------------------
extern "C" void kernel_launch(void* const* d_in, const int* in_sizes, int n_in,
                              void* d_out, int out_size) {
    const float* supports = (const float*)d_in[0];  // [2,512,512]
    const float* u        = (const float*)d_in[1];  // [2,512,64]
    const float* s        = (const float*)d_in[2];  // [2,64]
    const float* v        = (const float*)d_in[3];  // [2,512,64]
    const float* bias     = (const float*)d_in[4];  // [2,64]
    const float* inputs   = (const float*)d_in[5];  // [64,12,512,2]
    float* out = (float*)d_out;                     // [2,64,512,512]

    prep_kernel<<<dim3(8, 8, 3), 512>>>(supports, u, s, v, bias, inputs);
    main_kernel<<<dim3(NN / RN, Bn / BG), 256>>>(out);
}

// round 16
// speedup vs baseline: 1.1162x; 1.0379x over previous
#include <cuda_runtime.h>
#include <math.h>

#define En 2
#define NN 512
#define Bn 64
#define Tt 12
#define Kk 64
#define RN 4     // rows per block tile in main kernel
#define BG 4     // batches per block in main kernel
#define ESTR (Bn * NN * NN)   // e-stride in output

// Scratch (static device arrays: allocation-free)
__device__ __align__(16) float g_sup[En * NN * NN];      // relu(supports + adaptive)  (2 MB)
__device__ __align__(16) float g_nodesT[Bn * NN * Tt];   // normalized nodes, [b][n][t] (1.5 MB)
__device__ __align__(16) float g_nodesN[Bn * Tt * NN];   // normalized nodes, [b][t][n] (1.5 MB)

typedef unsigned long long ull;

// ---------------- packed f32x2 + MUFU helpers ----------------
__device__ __forceinline__ ull pack2(float a, float b) {
    ull r;
    asm("mov.b64 %0, {%1, %2};" : "=l"(r) : "f"(a), "f"(b));
    return r;
}
__device__ __forceinline__ void unpack2(ull p, float& a, float& b) {
    asm("mov.b64 {%0, %1}, %2;" : "=f"(a), "=f"(b) : "l"(p));
}
__device__ __forceinline__ ull fma2_(ull a, ull b, ull c) {
    ull d;
    asm("fma.rn.f32x2 %0, %1, %2, %3;" : "=l"(d) : "l"(a), "l"(b), "l"(c));
    return d;
}
__device__ __forceinline__ ull mul2_(ull a, ull b) {
    ull d;
    asm("mul.rn.f32x2 %0, %1, %2;" : "=l"(d) : "l"(a), "l"(b));
    return d;
}
__device__ __forceinline__ ull add2_(ull a, ull b) {
    ull d;
    asm("add.rn.f32x2 %0, %1, %2;" : "=l"(d) : "l"(a), "l"(b));
    return d;
}
__device__ __forceinline__ float sqrt_ap(float x) { float r; asm("sqrt.approx.f32 %0, %1;" : "=f"(r) : "f"(x)); return r; }
__device__ __forceinline__ float ex2_neg(float x) { float r; asm("ex2.approx.f32 %0, %1;"  : "=f"(r) : "f"(-x)); return r; }
__device__ __forceinline__ float rcp_ap(float x)  { float r; asm("rcp.approx.f32 %0, %1;"  : "=f"(r) : "f"(x)); return r; }
__device__ __forceinline__ float hadd2(ull p) {
    float a, b; unpack2(p, a, b); return a + b;
}
__device__ __forceinline__ ull shfl_xor64(ull v, int o) {
    unsigned lo = (unsigned)v, hi = (unsigned)(v >> 32);
    lo = __shfl_xor_sync(0xffffffffu, lo, o);
    hi = __shfl_xor_sync(0xffffffffu, hi, o);
    return ((ull)hi << 32) | lo;
}
// Evict-streaming 64-bit store: output is write-once, keep L2 for read reuse.
__device__ __forceinline__ void stg_cs64(float* p, ull v) {
    asm volatile("st.global.cs.b64 [%0], %1;" :: "l"(p), "l"(v) : "memory");
}

// ---------------------------------------------------------------------------
// Kernel A (fused prep), 512 threads:
//   z = 0,1 : g_sup[e] = relu(supports + u * diag(s*softplus(bias)) * v^T)
//   z = 2   : L2-normalize node histories -> g_nodesT [b][n][t] + g_nodesN [b][t][n]
// ---------------------------------------------------------------------------
__global__ void __launch_bounds__(512) prep_kernel(const float* __restrict__ supports,
                                                   const float* __restrict__ u,
                                                   const float* __restrict__ s,
                                                   const float* __restrict__ v,
                                                   const float* __restrict__ bias,
                                                   const float* __restrict__ inputs) {
    const int tid = threadIdx.x;

    if (blockIdx.z == 2) {
        const int i = (blockIdx.y * 8 + blockIdx.x) * 512 + tid;  // b*512 + n
        const int b = i >> 9, n = i & (NN - 1);
        float x[Tt];
        float ss = 0.f;
        #pragma unroll
        for (int t = 0; t < Tt; t++) {
            x[t] = inputs[(((b * Tt + t) * NN) + n) * 2];
            ss = fmaf(x[t], x[t], ss);
        }
        float inv = 1.0f / fmaxf(sqrtf(ss), 1e-12f);
        #pragma unroll
        for (int t = 0; t < Tt; t++) x[t] *= inv;
        float* dst = g_nodesT + (b * NN + n) * Tt;
        *(float4*)(dst)     = make_float4(x[0], x[1], x[2],  x[3]);
        *(float4*)(dst + 4) = make_float4(x[4], x[5], x[6],  x[7]);
        *(float4*)(dst + 8) = make_float4(x[8], x[9], x[10], x[11]);
        #pragma unroll
        for (int t = 0; t < Tt; t++)
            g_nodesN[(b * Tt + t) * NN + n] = x[t];
        return;
    }

    __shared__ float su_t[Kk][68];
    __shared__ float sv_t[Kk][68];
    __shared__ float ssc[Kk];

    const int e  = blockIdx.z;
    const int n0 = blockIdx.y * 64;
    const int m0 = blockIdx.x * 64;

    if (tid < 64) {
        float bx = bias[e * Kk + tid];
        float sp = (bx > 20.f) ? bx : log1pf(__expf(bx));   // softplus
        ssc[tid] = s[e * Kk + tid] * sp;
    }
    __syncthreads();

    #pragma unroll
    for (int j = 0; j < 2; j++) {
        int idx = tid + j * 512;
        int row = idx & 63;
        int kq  = idx >> 6;
        float4 uv = *(const float4*)(u + (e * NN + n0 + row) * Kk + kq * 4);
        float4 vv = *(const float4*)(v + (e * NN + m0 + row) * Kk + kq * 4);
        su_t[kq * 4 + 0][row] = uv.x * ssc[kq * 4 + 0];
        su_t[kq * 4 + 1][row] = uv.y * ssc[kq * 4 + 1];
        su_t[kq * 4 + 2][row] = uv.z * ssc[kq * 4 + 2];
        su_t[kq * 4 + 3][row] = uv.w * ssc[kq * 4 + 3];
        sv_t[kq * 4 + 0][row] = vv.x;
        sv_t[kq * 4 + 1][row] = vv.y;
        sv_t[kq * 4 + 2][row] = vv.z;
        sv_t[kq * 4 + 3][row] = vv.w;
    }
    __syncthreads();

    const int ry = (tid >> 4) << 1;
    const int rx = (tid & 15) << 2;
    float acc[2][4] = {};

    #pragma unroll
    for (int k = 0; k < 64; k++) {
        float2 a  = *(const float2*)&su_t[k][ry];
        float4 bq = *(const float4*)&sv_t[k][rx];
        acc[0][0] = fmaf(a.x, bq.x, acc[0][0]); acc[0][1] = fmaf(a.x, bq.y, acc[0][1]);
        acc[0][2] = fmaf(a.x, bq.z, acc[0][2]); acc[0][3] = fmaf(a.x, bq.w, acc[0][3]);
        acc[1][0] = fmaf(a.y, bq.x, acc[1][0]); acc[1][1] = fmaf(a.y, bq.y, acc[1][1]);
        acc[1][2] = fmaf(a.y, bq.z, acc[1][2]); acc[1][3] = fmaf(a.y, bq.w, acc[1][3]);
    }

    #pragma unroll
    for (int i = 0; i < 2; i++) {
        int base = (e * NN + n0 + ry + i) * NN + m0 + rx;
        float4 sp = *(const float4*)(supports + base);
        float4 o;
        o.x = fmaxf(sp.x + acc[i][0], 0.f);
        o.y = fmaxf(sp.y + acc[i][1], 0.f);
        o.z = fmaxf(sp.z + acc[i][2], 0.f);
        o.w = fmaxf(sp.w + acc[i][3], 0.f);
        *(float4*)(g_sup + base) = o;
    }
}

// ---------------------------------------------------------------------------
// Kernel C: fused main pass, software-pipelined (R8 structure).
// RN=4 rows x BOTH experts per block; xd staged once for all BG batches;
// xm2 LDGs issued before prev-batch writeout (latency shadow);
// 2 barriers per batch; output stores evict-streaming (write-once data).
// ---------------------------------------------------------------------------
__global__ void __launch_bounds__(256, 3)
main_kernel(float* __restrict__ out) {
    __shared__ ull ps[RN][256];                  // packed {e0,e1} partials, 8 KB
    __shared__ ull xd[BG * RN * Tt];             // packed {xn,xn}, all batches
    __shared__ ull invs[2][RN];                  // packed {iv_e0, iv_e1}, dbl-buffered

    const int tid  = threadIdx.x;
    const int lane = tid & 31;
    const int warp = tid >> 5;
    const int n0 = blockIdx.x * RN;
    const int b0 = blockIdx.y * BG;
    const int m0 = tid * 2;

    // sup (relu'd) in registers: batch-invariant, this thread's m-pair, both e
    ull sup0[RN], sup1[RN];
    #pragma unroll
    for (int r = 0; r < RN; r++) {
        sup0[r] = *(const ull*)(g_sup + (n0 + r) * NN + m0);
        sup1[r] = *(const ull*)(g_sup + NN * NN + (n0 + r) * NN + m0);
    }

    // Stage duplicated row-node tables for ALL batches (192 entries)
    if (tid < BG * RN * Tt) {
        int bl  = tid / (RN * Tt);
        int rem = tid - bl * (RN * Tt);
        int r = rem / Tt, t = rem - r * Tt;
        float xv = g_nodesT[(b0 + bl) * (NN * Tt) + (n0 + r) * Tt + t];
        xd[tid] = pack2(xv, xv);
    }
    __syncthreads();

    // 2 * (ln2^-1)^2
    const float C = 4.1627379620112154f;
    const ull CM = pack2(-C, -C);
    const ull CP = pack2( C,  C);

    ull val0[RN], val1[RN];

    #pragma unroll 2
    for (int bi = 0; bi < BG; ++bi) {
        // 1) issue this batch's xm2 loads FIRST (12 coalesced LDG.64)
        ull xm2[Tt];
        {
            const ull* xb = (const ull*)(g_nodesN + (b0 + bi) * (Tt * NN)) + tid;
            #pragma unroll
            for (int t = 0; t < Tt; t++)
                xm2[t] = xb[t * (NN / 2)];
        }

        // 2) previous batch's writeout in the LDG shadow (evict-streaming)
        if (bi > 0) {
            const int pv = (bi - 1) & 1;
            float* ob = out + ((b0 + bi - 1) * NN + n0) * NN + m0;
            #pragma unroll
            for (int r = 0; r < RN; r++) {
                float iv0, iv1;
                unpack2(invs[pv][r], iv0, iv1);
                stg_cs64(ob + r * NN,        mul2_(val0[r], pack2(iv0, iv0)));
                stg_cs64(ob + ESTR + r * NN, mul2_(val1[r], pack2(iv1, iv1)));
            }
        }

        // 3) compute vals + packed partial sums
        #pragma unroll
        for (int r = 0; r < RN; r++) {
            const ulonglong2* xdp = (const ulonglong2*)&xd[(bi * RN + r) * Tt];
            ulonglong2 q0 = xdp[0], q1 = xdp[1], q2 = xdp[2];
            ulonglong2 q3 = xdp[3], q4 = xdp[4], q5 = xdp[5];
            ull pa = mul2_(xm2[0], q0.x);
            ull pb = mul2_(xm2[1], q0.y);
            pa = fma2_(xm2[2],  q1.x, pa);  pb = fma2_(xm2[3],  q1.y, pb);
            pa = fma2_(xm2[4],  q2.x, pa);  pb = fma2_(xm2[5],  q2.y, pb);
            pa = fma2_(xm2[6],  q3.x, pa);  pb = fma2_(xm2[7],  q3.y, pb);
            pa = fma2_(xm2[8],  q4.x, pa);  pb = fma2_(xm2[9],  q4.y, pb);
            pa = fma2_(xm2[10], q5.x, pa);  pb = fma2_(xm2[11], q5.y, pb);
            ull inner2 = add2_(pa, pb);
            ull d2p = fma2_(inner2, CM, CP);  // (1.4427*d)^2 packed
            float d20, d21;
            unpack2(d2p, d20, d21);
            d20 = fmaxf(d20, 0.f);
            d21 = fmaxf(d21, 0.f);
            float f0 = ex2_neg(sqrt_ap(d20)) + 1.0f;
            float f1 = ex2_neg(sqrt_ap(d21)) + 1.0f;
            ull fp = pack2(f0, f1);

            val0[r] = mul2_(fp, sup0[r]);
            val1[r] = mul2_(fp, sup1[r]);
            ps[r][tid] = pack2(hadd2(val0[r]), hadd2(val1[r]));
        }
        __syncthreads();   // ps ready

        // 4) packed reduction: warps 0..RN-1 each reduce one row (256 ulls)
        if (warp < RN) {
            const ulonglong2* p = (const ulonglong2*)ps[warp];
            ulonglong2 a0 = p[lane];
            ulonglong2 a1 = p[lane + 32];
            ulonglong2 a2 = p[lane + 64];
            ulonglong2 a3 = p[lane + 96];
            ull s01 = add2_(add2_(a0.x, a0.y), add2_(a1.x, a1.y));
            ull s23 = add2_(add2_(a2.x, a2.y), add2_(a3.x, a3.y));
            ull sum = add2_(s01, s23);
            #pragma unroll
            for (int o = 16; o > 0; o >>= 1)
                sum = add2_(sum, shfl_xor64(sum, o));
            if (lane == 0) {
                float s0, s1;
                unpack2(sum, s0, s1);
                invs[bi & 1][warp] = pack2(rcp_ap(fmaxf(s0, 1e-12f)),
                                           rcp_ap(fmaxf(s1, 1e-12f)));
            }
        }
        __syncthreads();   // invs ready; guards ps reuse next iter
    }

    // Epilogue: last batch's writeout (evict-streaming)
    {
        const int pv = (BG - 1) & 1;
        float* ob = out + ((b0 + BG - 1) * NN + n0) * NN + m0;
        #pragma unroll
        for (int r = 0; r < RN; r++) {
            float iv0, iv1;
            unpack2(invs[pv][r], iv0, iv1);
            stg_cs64(ob + r * NN,        mul2_(val0[r], pack2(iv0, iv0)));
            stg_cs64(ob + ESTR + r * NN, mul2_(val1[r], pack2(iv1, iv1)));
        }
    }
}

// ---------------------------------------------------------------------------
extern "C" void kernel_launch(void* const* d_in, const int* in_sizes, int n_in,
                              void* d_out, int out_size) {
    const float* supports = (const float*)d_in[0];  // [2,512,512]
    const float* u        = (const float*)d_in[1];  // [2,512,64]
    const float* s        = (const float*)d_in[2];  // [2,64]
    const float* v        = (const float*)d_in[3];  // [2,512,64]
    const float* bias     = (const float*)d_in[4];  // [2,64]
    const float* inputs   = (const float*)d_in[5];  // [64,12,512,2]
    float* out = (float*)d_out;                     // [2,64,512,512]

    prep_kernel<<<dim3(8, 8, 3), 512>>>(supports, u, s, v, bias, inputs);
    main_kernel<<<dim3(NN / RN, Bn / BG), 256>>>(out);
}

// round 17
// speedup vs baseline: 1.1204x; 1.0037x over previous
#include <cuda_runtime.h>
#include <math.h>

#define En 2
#define NN 512
#define Bn 64
#define Tt 12
#define Kk 64
#define RN 4     // rows per block tile in main kernel
#define BG 4     // batches per block in main kernel
#define ESTR (Bn * NN * NN)   // e-stride in output

// Scratch (static device arrays: allocation-free)
__device__ __align__(16) float g_sup[En * NN * NN];      // relu(supports + adaptive)  (2 MB)
__device__ __align__(16) float g_nodesT[Bn * NN * Tt];   // normalized nodes, [b][n][t] (1.5 MB)
__device__ __align__(16) float g_nodesN[Bn * Tt * NN];   // normalized nodes, [b][t][n] (1.5 MB)

typedef unsigned long long ull;

// ---------------- packed f32x2 + MUFU helpers ----------------
__device__ __forceinline__ ull pack2(float a, float b) {
    ull r;
    asm("mov.b64 %0, {%1, %2};" : "=l"(r) : "f"(a), "f"(b));
    return r;
}
__device__ __forceinline__ void unpack2(ull p, float& a, float& b) {
    asm("mov.b64 {%0, %1}, %2;" : "=f"(a), "=f"(b) : "l"(p));
}
__device__ __forceinline__ ull fma2_(ull a, ull b, ull c) {
    ull d;
    asm("fma.rn.f32x2 %0, %1, %2, %3;" : "=l"(d) : "l"(a), "l"(b), "l"(c));
    return d;
}
__device__ __forceinline__ ull mul2_(ull a, ull b) {
    ull d;
    asm("mul.rn.f32x2 %0, %1, %2;" : "=l"(d) : "l"(a), "l"(b));
    return d;
}
__device__ __forceinline__ ull add2_(ull a, ull b) {
    ull d;
    asm("add.rn.f32x2 %0, %1, %2;" : "=l"(d) : "l"(a), "l"(b));
    return d;
}
__device__ __forceinline__ float sqrt_ap(float x) { float r; asm("sqrt.approx.f32 %0, %1;" : "=f"(r) : "f"(x)); return r; }
__device__ __forceinline__ float ex2_neg(float x) { float r; asm("ex2.approx.f32 %0, %1;"  : "=f"(r) : "f"(-x)); return r; }
__device__ __forceinline__ float rcp_ap(float x)  { float r; asm("rcp.approx.f32 %0, %1;"  : "=f"(r) : "f"(x)); return r; }
__device__ __forceinline__ float hadd2(ull p) {
    float a, b; unpack2(p, a, b); return a + b;
}
__device__ __forceinline__ ull shfl_xor64(ull v, int o) {
    unsigned lo = (unsigned)v, hi = (unsigned)(v >> 32);
    lo = __shfl_xor_sync(0xffffffffu, lo, o);
    hi = __shfl_xor_sync(0xffffffffu, hi, o);
    return ((ull)hi << 32) | lo;
}
// Evict-streaming 64-bit store: output is write-once, keep L2 for read reuse.
__device__ __forceinline__ void stg_cs64(float* p, ull v) {
    asm volatile("st.global.cs.b64 [%0], %1;" :: "l"(p), "l"(v) : "memory");
}

// ---------------------------------------------------------------------------
// Kernel A (fused prep), 512 threads:
//   z = 0,1 : g_sup[e] = relu(supports + u * diag(s*softplus(bias)) * v^T)
//   z = 2   : L2-normalize node histories -> g_nodesT [b][n][t] + g_nodesN [b][t][n]
// ---------------------------------------------------------------------------
__global__ void __launch_bounds__(512) prep_kernel(const float* __restrict__ supports,
                                                   const float* __restrict__ u,
                                                   const float* __restrict__ s,
                                                   const float* __restrict__ v,
                                                   const float* __restrict__ bias,
                                                   const float* __restrict__ inputs) {
    const int tid = threadIdx.x;

    if (blockIdx.z == 2) {
        const int i = (blockIdx.y * 8 + blockIdx.x) * 512 + tid;  // b*512 + n
        const int b = i >> 9, n = i & (NN - 1);
        float x[Tt];
        float ss = 0.f;
        #pragma unroll
        for (int t = 0; t < Tt; t++) {
            x[t] = inputs[(((b * Tt + t) * NN) + n) * 2];
            ss = fmaf(x[t], x[t], ss);
        }
        float inv = 1.0f / fmaxf(sqrtf(ss), 1e-12f);
        #pragma unroll
        for (int t = 0; t < Tt; t++) x[t] *= inv;
        float* dst = g_nodesT + (b * NN + n) * Tt;
        *(float4*)(dst)     = make_float4(x[0], x[1], x[2],  x[3]);
        *(float4*)(dst + 4) = make_float4(x[4], x[5], x[6],  x[7]);
        *(float4*)(dst + 8) = make_float4(x[8], x[9], x[10], x[11]);
        #pragma unroll
        for (int t = 0; t < Tt; t++)
            g_nodesN[(b * Tt + t) * NN + n] = x[t];
        return;
    }

    __shared__ float su_t[Kk][68];
    __shared__ float sv_t[Kk][68];
    __shared__ float ssc[Kk];

    const int e  = blockIdx.z;
    const int n0 = blockIdx.y * 64;
    const int m0 = blockIdx.x * 64;

    if (tid < 64) {
        float bx = bias[e * Kk + tid];
        float sp = (bx > 20.f) ? bx : log1pf(__expf(bx));   // softplus
        ssc[tid] = s[e * Kk + tid] * sp;
    }
    __syncthreads();

    #pragma unroll
    for (int j = 0; j < 2; j++) {
        int idx = tid + j * 512;
        int row = idx & 63;
        int kq  = idx >> 6;
        float4 uv = *(const float4*)(u + (e * NN + n0 + row) * Kk + kq * 4);
        float4 vv = *(const float4*)(v + (e * NN + m0 + row) * Kk + kq * 4);
        su_t[kq * 4 + 0][row] = uv.x * ssc[kq * 4 + 0];
        su_t[kq * 4 + 1][row] = uv.y * ssc[kq * 4 + 1];
        su_t[kq * 4 + 2][row] = uv.z * ssc[kq * 4 + 2];
        su_t[kq * 4 + 3][row] = uv.w * ssc[kq * 4 + 3];
        sv_t[kq * 4 + 0][row] = vv.x;
        sv_t[kq * 4 + 1][row] = vv.y;
        sv_t[kq * 4 + 2][row] = vv.z;
        sv_t[kq * 4 + 3][row] = vv.w;
    }
    __syncthreads();

    const int ry = (tid >> 4) << 1;
    const int rx = (tid & 15) << 2;
    float acc[2][4] = {};

    #pragma unroll
    for (int k = 0; k < 64; k++) {
        float2 a  = *(const float2*)&su_t[k][ry];
        float4 bq = *(const float4*)&sv_t[k][rx];
        acc[0][0] = fmaf(a.x, bq.x, acc[0][0]); acc[0][1] = fmaf(a.x, bq.y, acc[0][1]);
        acc[0][2] = fmaf(a.x, bq.z, acc[0][2]); acc[0][3] = fmaf(a.x, bq.w, acc[0][3]);
        acc[1][0] = fmaf(a.y, bq.x, acc[1][0]); acc[1][1] = fmaf(a.y, bq.y, acc[1][1]);
        acc[1][2] = fmaf(a.y, bq.z, acc[1][2]); acc[1][3] = fmaf(a.y, bq.w, acc[1][3]);
    }

    #pragma unroll
    for (int i = 0; i < 2; i++) {
        int base = (e * NN + n0 + ry + i) * NN + m0 + rx;
        float4 sp = *(const float4*)(supports + base);
        float4 o;
        o.x = fmaxf(sp.x + acc[i][0], 0.f);
        o.y = fmaxf(sp.y + acc[i][1], 0.f);
        o.z = fmaxf(sp.z + acc[i][2], 0.f);
        o.w = fmaxf(sp.w + acc[i][3], 0.f);
        *(float4*)(g_sup + base) = o;
    }
}

// ---------------------------------------------------------------------------
// Kernel C: fused main pass, software-pipelined (R8 structure + cs stores),
// PDL-gated so its launch/ramp overlaps prep's drain.
// RN=4 rows x BOTH experts per block; xd staged once for all BG batches;
// xm2 LDGs issued before prev-batch writeout (latency shadow);
// 2 barriers per batch; output stores evict-streaming (write-once data).
// ---------------------------------------------------------------------------
__global__ void __launch_bounds__(256, 3)
main_kernel(float* __restrict__ out) {
    __shared__ ull ps[RN][256];                  // packed {e0,e1} partials, 8 KB
    __shared__ ull xd[BG * RN * Tt];             // packed {xn,xn}, all batches
    __shared__ ull invs[2][RN];                  // packed {iv_e0, iv_e1}, dbl-buffered

    // PDL: wait for prep_kernel's writes (g_sup, g_nodesT, g_nodesN)
    cudaGridDependencySynchronize();

    const int tid  = threadIdx.x;
    const int lane = tid & 31;
    const int warp = tid >> 5;
    const int n0 = blockIdx.x * RN;
    const int b0 = blockIdx.y * BG;
    const int m0 = tid * 2;

    // sup (relu'd) in registers: batch-invariant, this thread's m-pair, both e
    ull sup0[RN], sup1[RN];
    #pragma unroll
    for (int r = 0; r < RN; r++) {
        sup0[r] = *(const ull*)(g_sup + (n0 + r) * NN + m0);
        sup1[r] = *(const ull*)(g_sup + NN * NN + (n0 + r) * NN + m0);
    }

    // Stage duplicated row-node tables for ALL batches (192 entries)
    if (tid < BG * RN * Tt) {
        int bl  = tid / (RN * Tt);
        int rem = tid - bl * (RN * Tt);
        int r = rem / Tt, t = rem - r * Tt;
        float xv = g_nodesT[(b0 + bl) * (NN * Tt) + (n0 + r) * Tt + t];
        xd[tid] = pack2(xv, xv);
    }
    __syncthreads();

    // 2 * (ln2^-1)^2
    const float C = 4.1627379620112154f;
    const ull CM = pack2(-C, -C);
    const ull CP = pack2( C,  C);

    ull val0[RN], val1[RN];

    #pragma unroll 2
    for (int bi = 0; bi < BG; ++bi) {
        // 1) issue this batch's xm2 loads FIRST (12 coalesced LDG.64)
        ull xm2[Tt];
        {
            const ull* xb = (const ull*)(g_nodesN + (b0 + bi) * (Tt * NN)) + tid;
            #pragma unroll
            for (int t = 0; t < Tt; t++)
                xm2[t] = xb[t * (NN / 2)];
        }

        // 2) previous batch's writeout in the LDG shadow (evict-streaming)
        if (bi > 0) {
            const int pv = (bi - 1) & 1;
            float* ob = out + ((b0 + bi - 1) * NN + n0) * NN + m0;
            #pragma unroll
            for (int r = 0; r < RN; r++) {
                float iv0, iv1;
                unpack2(invs[pv][r], iv0, iv1);
                stg_cs64(ob + r * NN,        mul2_(val0[r], pack2(iv0, iv0)));
                stg_cs64(ob + ESTR + r * NN, mul2_(val1[r], pack2(iv1, iv1)));
            }
        }

        // 3) compute vals + packed partial sums
        #pragma unroll
        for (int r = 0; r < RN; r++) {
            const ulonglong2* xdp = (const ulonglong2*)&xd[(bi * RN + r) * Tt];
            ulonglong2 q0 = xdp[0], q1 = xdp[1], q2 = xdp[2];
            ulonglong2 q3 = xdp[3], q4 = xdp[4], q5 = xdp[5];
            ull pa = mul2_(xm2[0], q0.x);
            ull pb = mul2_(xm2[1], q0.y);
            pa = fma2_(xm2[2],  q1.x, pa);  pb = fma2_(xm2[3],  q1.y, pb);
            pa = fma2_(xm2[4],  q2.x, pa);  pb = fma2_(xm2[5],  q2.y, pb);
            pa = fma2_(xm2[6],  q3.x, pa);  pb = fma2_(xm2[7],  q3.y, pb);
            pa = fma2_(xm2[8],  q4.x, pa);  pb = fma2_(xm2[9],  q4.y, pb);
            pa = fma2_(xm2[10], q5.x, pa);  pb = fma2_(xm2[11], q5.y, pb);
            ull inner2 = add2_(pa, pb);
            ull d2p = fma2_(inner2, CM, CP);  // (1.4427*d)^2 packed
            float d20, d21;
            unpack2(d2p, d20, d21);
            d20 = fmaxf(d20, 0.f);
            d21 = fmaxf(d21, 0.f);
            float f0 = ex2_neg(sqrt_ap(d20)) + 1.0f;
            float f1 = ex2_neg(sqrt_ap(d21)) + 1.0f;
            ull fp = pack2(f0, f1);

            val0[r] = mul2_(fp, sup0[r]);
            val1[r] = mul2_(fp, sup1[r]);
            ps[r][tid] = pack2(hadd2(val0[r]), hadd2(val1[r]));
        }
        __syncthreads();   // ps ready

        // 4) packed reduction: warps 0..RN-1 each reduce one row (256 ulls)
        if (warp < RN) {
            const ulonglong2* p = (const ulonglong2*)ps[warp];
            ulonglong2 a0 = p[lane];
            ulonglong2 a1 = p[lane + 32];
            ulonglong2 a2 = p[lane + 64];
            ulonglong2 a3 = p[lane + 96];
            ull s01 = add2_(add2_(a0.x, a0.y), add2_(a1.x, a1.y));
            ull s23 = add2_(add2_(a2.x, a2.y), add2_(a3.x, a3.y));
            ull sum = add2_(s01, s23);
            #pragma unroll
            for (int o = 16; o > 0; o >>= 1)
                sum = add2_(sum, shfl_xor64(sum, o));
            if (lane == 0) {
                float s0, s1;
                unpack2(sum, s0, s1);
                invs[bi & 1][warp] = pack2(rcp_ap(fmaxf(s0, 1e-12f)),
                                           rcp_ap(fmaxf(s1, 1e-12f)));
            }
        }
        __syncthreads();   // invs ready; guards ps reuse next iter
    }

    // Epilogue: last batch's writeout (evict-streaming)
    {
        const int pv = (BG - 1) & 1;
        float* ob = out + ((b0 + BG - 1) * NN + n0) * NN + m0;
        #pragma unroll
        for (int r = 0; r < RN; r++) {
            float iv0, iv1;
            unpack2(invs[pv][r], iv0, iv1);
            stg_cs64(ob + r * NN,        mul2_(val0[r], pack2(iv0, iv0)));
            stg_cs64(ob + ESTR + r * NN, mul2_(val1[r], pack2(iv1, iv1)));
        }
    }
}

// ---------------------------------------------------------------------------
extern "C" void kernel_launch(void* const* d_in, const int* in_sizes, int n_in,
                              void* d_out, int out_size) {
    const float* supports = (const float*)d_in[0];  // [2,512,512]
    const float* u        = (const float*)d_in[1];  // [2,512,64]
    const float* s        = (const float*)d_in[2];  // [2,64]
    const float* v        = (const float*)d_in[3];  // [2,512,64]
    const float* bias     = (const float*)d_in[4];  // [2,64]
    const float* inputs   = (const float*)d_in[5];  // [64,12,512,2]
    float* out = (float*)d_out;                     // [2,64,512,512]

    prep_kernel<<<dim3(8, 8, 3), 512>>>(supports, u, s, v, bias, inputs);

    // PDL launch: main may ramp while prep drains; in-kernel
    // cudaGridDependencySynchronize() gates consumption of prep outputs.
    cudaLaunchConfig_t cfg = {};
    cfg.gridDim  = dim3(NN / RN, Bn / BG);
    cfg.blockDim = dim3(256);
    cudaLaunchAttribute attr[1];
    attr[0].id = cudaLaunchAttributeProgrammaticStreamSerialization;
    attr[0].val.programmaticStreamSerializationAllowed = 1;
    cfg.attrs = attr;
    cfg.numAttrs = 1;
    cudaLaunchKernelEx(&cfg, main_kernel, out);
}